// round 17
// baseline (speedup 1.0000x reference)
#include <cuda_runtime.h>
#include <cuda_fp16.h>
#include <stdint.h>

// ---------------------------------------------------------------------------
// MultiheadAttention: B=2, S=2048, D=1024, H=16, hd=64
// Round 17:
//  * attention: 64-key cp.async stages, two 32-key halves per stage ->
//    syncthreads / wait / issue rounds halve (64 -> 32); numerics identical
//  * conversion kernels merged into a single launch (3 inputs + 4 weights)
//  * projections / ldmatrix / layouts unchanged from round 16
// ---------------------------------------------------------------------------

#define D_MODEL 1024
#define SEQ     2048
#define ELEMS   4194304UL   // 4096*1024
#define WEL     1048576UL   // 1024*1024

// all scratch is fp16 (halves)
#define O_IN(i)  ((size_t)(i) * ELEMS)            // inputs, fp16 single
#define O_W(i)   (3 * ELEMS + (size_t)(i) * WEL)  // weights, fp16 single
#define BASE2    (3 * ELEMS + 4 * WEL)
#define O_Q      (BASE2)                 // fp16 single [bh,s,d], scaled
#define O_K      (BASE2 + 1 * ELEMS)     // fp16 single [bh,s,d]
#define O_VT     (BASE2 + 2 * ELEMS)     // fp16 single [bh,d,s]
#define O_C      (BASE2 + 3 * ELEMS)     // fp16 single context [b,s,D]
#define H_TOTAL  (BASE2 + 4 * ELEMS)

__device__ __align__(16) __half g_h[H_TOTAL];

#define QSCALE 0.18033688011112042f   // (1/sqrt(64)) * log2(e)

// ---------------------------------------------------------------------------
// helpers
// ---------------------------------------------------------------------------
__device__ __forceinline__ void mma_f16(float c[4], const uint32_t a[4],
                                        const uint32_t b[2]) {
    asm("mma.sync.aligned.m16n8k16.row.col.f32.f16.f16.f32 "
        "{%0,%1,%2,%3}, {%4,%5,%6,%7}, {%8,%9}, {%0,%1,%2,%3};\n"
        : "+f"(c[0]), "+f"(c[1]), "+f"(c[2]), "+f"(c[3])
        : "r"(a[0]), "r"(a[1]), "r"(a[2]), "r"(a[3]), "r"(b[0]), "r"(b[1]));
}

__device__ __forceinline__ void ldsm_x4(uint32_t& r0, uint32_t& r1,
                                        uint32_t& r2, uint32_t& r3,
                                        uint32_t addr) {
    asm volatile(
        "ldmatrix.sync.aligned.m8n8.x4.shared.b16 {%0,%1,%2,%3}, [%4];"
        : "=r"(r0), "=r"(r1), "=r"(r2), "=r"(r3) : "r"(addr));
}

__device__ __forceinline__ uint32_t pack_f16(float x, float y) {
    __half2 h = __floats2half2_rn(x, y);
    return *reinterpret_cast<uint32_t*>(&h);
}

__device__ __forceinline__ float fast_exp2(float x) {
    float y;
    asm("ex2.approx.f32 %0, %1;" : "=f"(y) : "f"(x));
    return y;
}

__device__ __forceinline__ uint32_t smem_u32(const void* p) {
    uint32_t a;
    asm("{ .reg .u64 t; cvta.to.shared.u64 t, %1; cvt.u32.u64 %0, t; }"
        : "=r"(a) : "l"(p));
    return a;
}

__device__ __forceinline__ void cpa16(uint32_t dst, const void* src) {
    asm volatile("cp.async.cg.shared.global [%0], [%1], 16;\n"
                 :: "r"(dst), "l"(src) : "memory");
}
__device__ __forceinline__ void cpa_commit() {
    asm volatile("cp.async.commit_group;\n" ::: "memory");
}
template <int N>
__device__ __forceinline__ void cpa_wait() {
    asm volatile("cp.async.wait_group %0;\n" :: "n"(N) : "memory");
}

// ---------------------------------------------------------------------------
// merged conversion kernel: fp32 -> fp16 single
//   blockIdx.y 0..2: inputs (query/key/value, ELEMS each)
//   blockIdx.y 3..6: weights (Wq/Wk/Wv/Wo, WEL each)
// ---------------------------------------------------------------------------
__global__ void conv_all(const float* __restrict__ q,
                         const float* __restrict__ k,
                         const float* __restrict__ v,
                         const float* __restrict__ wq,
                         const float* __restrict__ wk,
                         const float* __restrict__ wv,
                         const float* __restrict__ wo) {
    const int y = blockIdx.y;
    const float* src;
    size_t off;
    int n4;
    if (y < 3) {
        src = (y == 0) ? q : (y == 1) ? k : v;
        off = O_IN(y);
        n4 = (int)(ELEMS / 4);
    } else {
        int z = y - 3;
        src = (z == 0) ? wq : (z == 1) ? wk : (z == 2) ? wv : wo;
        off = O_W(z);
        n4 = (int)(WEL / 4);
    }
    int i = blockIdx.x * blockDim.x + threadIdx.x;
    if (i >= n4) return;
    float4 val = ((const float4*)src)[i];
    *(uint2*)(g_h + off + (size_t)i * 4) =
        make_uint2(pack_f16(val.x, val.y), pack_f16(val.z, val.w));
}

// ---------------------------------------------------------------------------
// Projection GEMM (1-term fp16):  Y[4096,1024] = Xh @ Wh^T + bias
//   CTA tile 128x128, 8 warps (2x4), warp tile 64x32, k-step 32,
//   double-buffered cp.async, ldmatrix fragment loads.
//   mode 0/1: q/k -> fp16 single [bh,s,d] (scale applied);
//   mode 2: v -> fp16 single transposed [bh,d,s]; mode 3: out -> fp32.
// ---------------------------------------------------------------------------
#define ASTRP 40
#define BSTRP 40
#define PA_E (128 * ASTRP)                // 5120 halves
#define PB_E (128 * BSTRP)                // 5120 halves
#define PJ_STAGE_B ((PA_E + PB_E) * 2)    // 20480 bytes
#define PJ_SMEM (2 * PJ_STAGE_B)          // 40960 bytes

__device__ __forceinline__ void gemm_body(
    size_t x_off, size_t w_off,
    const float* __restrict__ bias, int mode, float scale,
    size_t off_o, float* __restrict__ of32, char* smem) {
    const int tid = threadIdx.x, lane = tid & 31, w = tid >> 5;
    const int warpM = w >> 2, warpN = w & 3;
    const int row0 = blockIdx.y * 128, col0 = blockIdx.x * 128;
    const int ar = lane >> 2, ac = (lane & 3) * 2;
    const uint32_t sb = smem_u32(smem);

    const __half* XH = g_h + x_off;
    const __half* WH = g_h + w_off;

    // ldmatrix lane offsets (halves)
    const int a_off = ((lane & 7) + ((lane >> 3) & 1) * 8) * ASTRP +
                      (lane >> 4) * 8;                       // A operand
    const int b_off = ((lane & 7) + ((lane >> 4) << 3)) * BSTRP +
                      ((lane >> 3) & 1) * 8;                 // B operand

    auto issue = [&](int st, int buf) {
        const int k0 = st * 32;
        const uint32_t db = sb + buf * PJ_STAGE_B;
#pragma unroll
        for (int i = 0; i < 4; i++) {
            int c = tid + i * 256;
            if (c < 512) {
                int r = c >> 2, c8 = (c & 3) * 8;
                cpa16(db + (uint32_t)(r * ASTRP + c8) * 2,
                      XH + (size_t)(row0 + r) * D_MODEL + k0 + c8);
            } else {
                int b2 = c - 512;
                int r = b2 >> 2, c8 = (b2 & 3) * 8;
                cpa16(db + PA_E * 2 + (uint32_t)(r * BSTRP + c8) * 2,
                      WH + (size_t)(col0 + r) * D_MODEL + k0 + c8);
            }
        }
        cpa_commit();
    };

    float acc[4][4][4];
#pragma unroll
    for (int i = 0; i < 4; i++)
#pragma unroll
        for (int j = 0; j < 4; j++)
#pragma unroll
            for (int e = 0; e < 4; e++) acc[i][j][e] = 0.f;

    issue(0, 0);

    for (int it = 0; it < 32; it++) {
        const int buf = it & 1;
        cpa_wait<0>();
        __syncthreads();
        if (it < 31) issue(it + 1, buf ^ 1);

        const uint32_t sA = sb + buf * PJ_STAGE_B;
        const uint32_t sB = sA + PA_E * 2;
        const uint32_t aA = sA + (uint32_t)(warpM * 64 * ASTRP + a_off) * 2;
        const uint32_t bA = sB + (uint32_t)(warpN * 32 * BSTRP + b_off) * 2;

#pragma unroll
        for (int kk = 0; kk < 32; kk += 16) {
            uint32_t ah[4][4], bhf[4][2];
#pragma unroll
            for (int mi = 0; mi < 4; mi++)
                ldsm_x4(ah[mi][0], ah[mi][1], ah[mi][2], ah[mi][3],
                        aA + (uint32_t)(mi * 16 * ASTRP + kk) * 2);
#pragma unroll
            for (int np = 0; np < 2; np++)
                ldsm_x4(bhf[2 * np][0], bhf[2 * np][1],
                        bhf[2 * np + 1][0], bhf[2 * np + 1][1],
                        bA + (uint32_t)(np * 16 * BSTRP + kk) * 2);
#pragma unroll
            for (int mi = 0; mi < 4; mi++)
#pragma unroll
                for (int ni = 0; ni < 4; ni++)
                    mma_f16(acc[mi][ni], ah[mi], bhf[ni]);
        }
    }

    // epilogue
#pragma unroll
    for (int mi = 0; mi < 4; mi++) {
#pragma unroll
        for (int ni = 0; ni < 4; ni++) {
            int Rr = row0 + warpM * 64 + mi * 16 + ar;
            int C = col0 + warpN * 32 + ni * 8 + ac;
            float bv0 = bias[C], bv1 = bias[C + 1];
#pragma unroll
            for (int hf = 0; hf < 2; hf++) {
                int Rw = Rr + hf * 8;
                float v0 = (acc[mi][ni][hf * 2 + 0] + bv0) * scale;
                float v1 = (acc[mi][ni][hf * 2 + 1] + bv1) * scale;
                if (mode == 3) {
                    float2 o = make_float2(v0, v1);
                    *(float2*)(of32 + (size_t)Rw * D_MODEL + C) = o;
                } else {
                    int b = Rw >> 11, s2 = Rw & 2047;
                    int h = C >> 6, d = C & 63;
                    if (mode <= 1) {
                        size_t idx = ((size_t)(b * 16 + h) * SEQ + s2) * 64 + d;
                        *(uint32_t*)(g_h + off_o + idx) = pack_f16(v0, v1);
                    } else {
                        size_t idx = ((size_t)(b * 16 + h) * 64 + d) * SEQ + s2;
                        g_h[off_o + idx] = __float2half(v0);
                        g_h[off_o + idx + SEQ] = __float2half(v1);
                    }
                }
            }
        }
    }
}

__global__ __launch_bounds__(256, 2) void proj_qkv(
    const float* __restrict__ bq, const float* __restrict__ bk,
    const float* __restrict__ bv) {
    extern __shared__ char smem[];
    const int z = blockIdx.z;
    const size_t oo[3] = {O_Q, O_K, O_VT};
    const float* bias = (z == 0) ? bq : (z == 1) ? bk : bv;
    const float scale = (z == 0) ? QSCALE : 1.0f;
    gemm_body(O_IN(z), O_W(z), bias, z, scale, oo[z], nullptr, smem);
}

__global__ __launch_bounds__(256, 2) void proj_out(
    const float* __restrict__ bo, float* __restrict__ out) {
    extern __shared__ char smem[];
    gemm_body(O_C, O_W(3), bo, 3, 1.0f, 0, out, smem);
}

// ---------------------------------------------------------------------------
// Attention, fp16 1-term, ldmatrix, 64-key double-buffered stages with two
// 32-key compute halves per stage (one syncthreads per 64 keys).
// Grid (32 bh, 32 q-tiles of 64 rows), 128 threads, 4 CTAs/SM.
// ---------------------------------------------------------------------------
#define KSTR2 72                        // halves: 64 + 8 pad (144B rows)
#define VSTR2 72                        // halves: 64 keys + 8 pad
#define K_TILE_E (64 * KSTR2)           // 4608 halves (64 key rows)
#define V_TILE_E (64 * VSTR2)           // 4608 halves (64 d rows)
#define AT_STAGE_E (K_TILE_E + V_TILE_E)
#define AT_STAGE_B (AT_STAGE_E * 2)     // 18432 bytes
#define AT_SMEM (2 * AT_STAGE_B)        // 36864 bytes

__global__ __launch_bounds__(128, 4) void attn_kernel() {
    extern __shared__ __half at_smem[];

    const int bh = blockIdx.x;
    const int q0 = blockIdx.y * 64;
    const int tid = threadIdx.x, lane = tid & 31, w = tid >> 5;
    const int ar = lane >> 2, ac = (lane & 3) * 2;
    const size_t base = (size_t)bh * SEQ * 64;

    const __half* qp = g_h + O_Q + base;
    const __half* khp = g_h + O_K + base;
    const __half* vhp = g_h + O_VT + base;   // [d, s]

    const uint32_t sb = smem_u32(at_smem);

    // ldmatrix B-operand lane offset (rows = n, contiguous along k)
    const int b_row = (lane & 7) + ((lane >> 4) << 3);
    const int b_col = ((lane >> 3) & 1) * 8;
    const uint32_t kAddr0 = sb + (uint32_t)(b_row * KSTR2 + b_col) * 2;
    const uint32_t vAddr0 = sb + K_TILE_E * 2 +
                            (uint32_t)(b_row * VSTR2 + b_col) * 2;

    // one 64-key stage = 1024 16B chunks (K 512, V 512); 8 per thread
    auto issue = [&](int jt, int buf) {
        const int j0 = jt * 64;
        const uint32_t db = sb + buf * AT_STAGE_B;
#pragma unroll
        for (int i = 0; i < 8; i++) {
            int c = tid + i * 128;
            if (c < 512) {   // K: 64 rows x 8 chunks
                int r = c >> 3, c8 = (c & 7) * 8;
                cpa16(db + (uint32_t)(r * KSTR2 + c8) * 2,
                      khp + (size_t)(j0 + r) * 64 + c8);
            } else {          // V: 64 d-rows x 8 chunks
                int v2 = c - 512;
                int r = v2 >> 3, c8 = (v2 & 7) * 8;
                cpa16(db + K_TILE_E * 2 + (uint32_t)(r * VSTR2 + c8) * 2,
                      vhp + (size_t)r * SEQ + j0 + c8);
            }
        }
        cpa_commit();
    };

    issue(0, 0);

    // preload Q fragments (fp16 single; q pre-scaled by log2e/8)
    uint32_t qf[4][4];
    {
        const __half* q1 = qp + (size_t)(q0 + w * 16) * 64;
#pragma unroll
        for (int ks = 0; ks < 4; ks++) {
            int o = ks * 16 + ac;
            qf[ks][0] = *(const uint32_t*)(q1 + ar * 64 + o);
            qf[ks][1] = *(const uint32_t*)(q1 + (ar + 8) * 64 + o);
            qf[ks][2] = *(const uint32_t*)(q1 + ar * 64 + o + 8);
            qf[ks][3] = *(const uint32_t*)(q1 + (ar + 8) * 64 + o + 8);
        }
    }

    float o_acc[8][4];
#pragma unroll
    for (int i = 0; i < 8; i++)
#pragma unroll
        for (int e = 0; e < 4; e++) o_acc[i][e] = 0.f;
    float l0 = 0.f, l1 = 0.f;

    for (int jt = 0; jt < 32; jt++) {
        const int buf = jt & 1;
        cpa_wait<0>();
        __syncthreads();
        if (jt < 31) issue(jt + 1, buf ^ 1);

        const uint32_t kA = kAddr0 + buf * AT_STAGE_B;
        const uint32_t vA = vAddr0 + buf * AT_STAGE_B;

        // two 32-key halves per stage
#pragma unroll
        for (int h2 = 0; h2 < 2; h2++) {
            const uint32_t kAh = kA + (uint32_t)(h2 * 32 * KSTR2) * 2;

            // scores (32 keys): S = qh * kh
            float s[4][4];
#pragma unroll
            for (int i = 0; i < 4; i++)
#pragma unroll
                for (int e = 0; e < 4; e++) s[i][e] = 0.f;

#pragma unroll
            for (int ks = 0; ks < 4; ks++) {
                uint32_t bhf[4][2];
#pragma unroll
                for (int np = 0; np < 2; np++)
                    ldsm_x4(bhf[2 * np][0], bhf[2 * np][1],
                            bhf[2 * np + 1][0], bhf[2 * np + 1][1],
                            kAh + (uint32_t)(np * 16 * KSTR2 + ks * 16) * 2);
#pragma unroll
                for (int ni = 0; ni < 4; ni++) mma_f16(s[ni], qf[ks], bhf[ni]);
            }

            // P = 2^s; per-lane partial row sums
#pragma unroll
            for (int ni = 0; ni < 4; ni++) {
                s[ni][0] = fast_exp2(s[ni][0]);
                s[ni][1] = fast_exp2(s[ni][1]);
                s[ni][2] = fast_exp2(s[ni][2]);
                s[ni][3] = fast_exp2(s[ni][3]);
                l0 += s[ni][0] + s[ni][1];
                l1 += s[ni][2] + s[ni][3];
            }

            // P@V: O += ph * vh  (key cols h2*32 + kg*16 of the V tile)
#pragma unroll
            for (int kg = 0; kg < 2; kg++) {
                uint32_t ph[4];
                ph[0] = pack_f16(s[2 * kg][0], s[2 * kg][1]);
                ph[1] = pack_f16(s[2 * kg][2], s[2 * kg][3]);
                ph[2] = pack_f16(s[2 * kg + 1][0], s[2 * kg + 1][1]);
                ph[3] = pack_f16(s[2 * kg + 1][2], s[2 * kg + 1][3]);

                uint32_t vb[8][2];
#pragma unroll
                for (int gp = 0; gp < 4; gp++)
                    ldsm_x4(vb[2 * gp][0], vb[2 * gp][1],
                            vb[2 * gp + 1][0], vb[2 * gp + 1][1],
                            vA + (uint32_t)(gp * 16 * VSTR2 + h2 * 32 +
                                            kg * 16) * 2);
#pragma unroll
                for (int ni = 0; ni < 8; ni++)
                    mma_f16(o_acc[ni], ph, vb[ni]);
            }
        }
    }

    l0 += __shfl_xor_sync(0xffffffffu, l0, 1);
    l0 += __shfl_xor_sync(0xffffffffu, l0, 2);
    l1 += __shfl_xor_sync(0xffffffffu, l1, 1);
    l1 += __shfl_xor_sync(0xffffffffu, l1, 2);
    float inv0 = 1.f / l0, inv1 = 1.f / l1;

    // normalize and write fp16 single context [b, s, h*64+d]
    const int b = bh >> 4, h = bh & 15;
    const int Rg = q0 + w * 16 + ar;
#pragma unroll
    for (int ni = 0; ni < 8; ni++) {
        int col = h * 64 + ni * 8 + ac;
        size_t r0i = (size_t)(b * SEQ + Rg) * D_MODEL + col;
        size_t r1i = (size_t)(b * SEQ + Rg + 8) * D_MODEL + col;
        *(uint32_t*)(g_h + O_C + r0i) =
            pack_f16(o_acc[ni][0] * inv0, o_acc[ni][1] * inv0);
        *(uint32_t*)(g_h + O_C + r1i) =
            pack_f16(o_acc[ni][2] * inv1, o_acc[ni][3] * inv1);
    }
}

// ---------------------------------------------------------------------------
// launch
// ---------------------------------------------------------------------------
extern "C" void kernel_launch(void* const* d_in, const int* in_sizes, int n_in,
                              void* d_out, int out_size) {
    const float* query = (const float*)d_in[0];
    const float* key_i = (const float*)d_in[1];
    const float* value = (const float*)d_in[2];
    const float* Wq = (const float*)d_in[3];
    const float* bq = (const float*)d_in[4];
    const float* Wk = (const float*)d_in[5];
    const float* bk = (const float*)d_in[6];
    const float* Wv = (const float*)d_in[7];
    const float* bv = (const float*)d_in[8];
    const float* Wo = (const float*)d_in[9];
    const float* bo = (const float*)d_in[10];
    float* out = (float*)d_out;

    static bool attr_done = false;
    if (!attr_done) {
        cudaFuncSetAttribute(proj_qkv,
                             cudaFuncAttributeMaxDynamicSharedMemorySize,
                             PJ_SMEM);
        cudaFuncSetAttribute(proj_out,
                             cudaFuncAttributeMaxDynamicSharedMemorySize,
                             PJ_SMEM);
        cudaFuncSetAttribute(attn_kernel,
                             cudaFuncAttributeMaxDynamicSharedMemorySize,
                             AT_SMEM);
        attr_done = true;
    }

    conv_all<<<dim3((int)(ELEMS / 4 / 256), 7), 256>>>(query, key_i, value,
                                                       Wq, Wk, Wv, Wo);

    proj_qkv<<<dim3(8, 32, 3), 256, PJ_SMEM>>>(bq, bk, bv);

    attn_kernel<<<dim3(32, 32), 128, AT_SMEM>>>();

    proj_out<<<dim3(8, 32), 256, PJ_SMEM>>>(bo, out);
    (void)in_sizes; (void)n_in; (void)out_size;
}